// round 4
// baseline (speedup 1.0000x reference)
#include <cuda_runtime.h>
#include <math.h>

// B=4, D1=D2=D3=64, CIN=COUT=32, M1=M2=M3=8
// Exact linear-algebra pipeline (no full FFTs):
//   A[bm,d2,p,c]  = sum_d3 x[bm,d2,d3,c] e^{-2pi i p d3/64}   (m<8,p<8)
//   Bs[bm,n,p,c]  = sum_d2 A e^{-2pi i n d2/64}               (n<8)
//   U1[bm,n,p,co] = sum_c Bs * M_p[c,co]
//   out[bm,d2,d3,co] = Re sum_{n,p} U1 e^{+2pi i (n d2 + p d3)/64}; y[:,8:]=0.
// The 117MB zero region is written by extra blocks spread across all kernels.

#define NB 4
#define NC 32
#define NM 8

#define ZREG 1835008ull           // float4 per zero region (one per b)
#define Z1 2202112ull             // K1 share end (30%)
#define Z2 3302912ull             // K2 share end (+15%)
#define Z3 5137920ull             // K3 share end (+25%)
#define Z4 7340032ull             // total (+30%)

__device__ float2 g_A  [NB*NM*64*NM*NC];   // [bm][d2][p][c]  4 MB
__device__ float2 g_U1 [NB*NM*NM*NM*NC];   // [bm][n][p][co]  512 KB
__device__ float2 g_Ws [NM*NC*NC];         // [p][k][o]
__device__ float2 g_M  [NM*NC*NC];         // [p][c][co]

// Zero-fill helper: grid-stride over float4 indices [lo,hi) of the flattened
// zero region (4 regions of ZREG float4: out[b, 8:64, :, :, :]).
__device__ __forceinline__ void zero_range(float4* o4, size_t lo, size_t hi,
                                           int zb, int nzb, int nthreads, int t) {
    const float4 z = make_float4(0.f, 0.f, 0.f, 0.f);
    size_t step = (size_t)nzb * nthreads;
    #pragma unroll
    for (int b = 0; b < 4; b++) {
        size_t rlo = (size_t)b * ZREG;
        size_t rhi = rlo + ZREG;
        size_t s = lo > rlo ? lo : rlo;
        size_t e = hi < rhi ? hi : rhi;
        float4* base = o4 + (size_t)(b * 64 + 8) * 32768 - rlo;
        for (size_t i = s + (size_t)zb * nthreads + t; i < e; i += step)
            __stcs(base + i, z);
    }
}

// ---------------------------------------------------------------------------
// K1: blocks [0,2048): d3 forward DFT (64 -> 8 modes), one per (bm,d2).
//     blocks [2048,2080): Wsum[p][k][o] = sum_ij (wr+i wi)[k][o][i][j][p]
//     blocks [2080,2336): zero-fill share [0, Z1)
// ---------------------------------------------------------------------------
__global__ void fwd_d3(const float* __restrict__ x,
                       const float* __restrict__ wr, const float* __restrict__ wi,
                       float* __restrict__ out) {
    int t = threadIdx.x;                              // 256
    if (blockIdx.x >= 2080) {
        zero_range((float4*)out, 0, Z1, blockIdx.x - 2080, 256, 256, t);
        return;
    }
    if (blockIdx.x >= 2048) {
        int g = (blockIdx.x - 2048) * 256 + t;        // 0..8191
        int p = g & 7;
        int o = (g >> 3) & 31;
        int k = g >> 8;
        float sr = 0.f, si = 0.f;
        int base = (k * 32 + o) * 512 + p;
        #pragma unroll 8
        for (int ij = 0; ij < 64; ij++) {
            sr += wr[base + ij * 8];
            si += wi[base + ij * 8];
        }
        g_Ws[(p * 32 + k) * 32 + o] = make_float2(sr, si);
        return;
    }
    __shared__ float  xs[2048];
    __shared__ float2 tw[64];
    if (t < 64) {
        float s, c;
        sincospif(-(float)t / 32.0f, &s, &c);         // e^{-2pi i t/64}
        tw[t] = make_float2(c, s);
    }
    int blk = blockIdx.x;                             // (b*8+m)*64 + d2
    int bm = blk >> 6;
    int d2 = blk & 63;
    int b = bm >> 3, m = bm & 7;
    const float4* xin = (const float4*)(x + ((size_t)(b * 64 + m) * 64 + d2) * 2048);
    float4* xs4 = (float4*)xs;
    xs4[t]       = __ldcs(xin + t);
    xs4[t + 256] = __ldcs(xin + t + 256);
    __syncthreads();
    int p = t >> 5, c = t & 31;
    float ar = 0.f, ai = 0.f;
    #pragma unroll 8
    for (int d3 = 0; d3 < 64; d3++) {
        float v = xs[d3 * 32 + c];
        float2 e = tw[(p * d3) & 63];
        ar += v * e.x;
        ai += v * e.y;
    }
    g_A[(size_t)blk * 256 + t] = make_float2(ar, ai);
}

// ---------------------------------------------------------------------------
// K2: blocks [0,8): M_p = (1/131072) IDFT32 o Wsum_p o DFT32.
//     blocks [8,136): zero-fill share [Z1, Z2).   blockDim = 1024
// ---------------------------------------------------------------------------
__global__ void prep_M(float* __restrict__ out) {
    int t = threadIdx.x;                              // 1024
    if (blockIdx.x >= 8) {
        zero_range((float4*)out, Z1, Z2, blockIdx.x - 8, 128, 1024, t);
        return;
    }
    __shared__ float2 tw32[32];
    __shared__ float2 Ws[1024];
    __shared__ float2 P[1024];
    int p = blockIdx.x;
    if (t < 32) {
        float s, c;
        sincospif(-(float)t / 16.0f, &s, &c);
        tw32[t] = make_float2(c, s);
    }
    Ws[t] = g_Ws[p * 1024 + t];
    __syncthreads();
    {
        int o = t & 31, c = t >> 5;
        float2 acc = make_float2(0.f, 0.f);
        #pragma unroll 8
        for (int k = 0; k < 32; k++) {
            float2 e = tw32[(k * c) & 31];
            float2 w = Ws[k * 32 + o];
            acc.x += e.x * w.x - e.y * w.y;
            acc.y += e.x * w.y + e.y * w.x;
        }
        P[c * 32 + o] = acc;
    }
    __syncthreads();
    {
        int co = t & 31, c = t >> 5;
        float2 acc = make_float2(0.f, 0.f);
        #pragma unroll 8
        for (int o = 0; o < 32; o++) {
            float2 e = tw32[(o * co) & 31];
            float2 v = P[c * 32 + o];
            acc.x += v.x * e.x + v.y * e.y;   // v * conj(e)
            acc.y += v.y * e.x - v.x * e.y;
        }
        const float scale = 1.0f / 131072.0f;
        g_M[(p * 32 + c) * 32 + co] = make_float2(acc.x * scale, acc.y * scale);
    }
}

// ---------------------------------------------------------------------------
// K3: blocks [0,256): d2 forward DFT + channel mix, one per (bm,p).
//     blocks [256,512): zero-fill share [Z2, Z3).
// ---------------------------------------------------------------------------
__global__ void fwd_d2_mix(float* __restrict__ out) {
    int t = threadIdx.x;
    if (blockIdx.x >= 256) {
        zero_range((float4*)out, Z2, Z3, blockIdx.x - 256, 256, 256, t);
        return;
    }
    __shared__ float2 tw[64];
    __shared__ float2 As[64 * 32];   // [d2][c] 16 KB
    __shared__ float2 Ms[32 * 32];   // [c][co]  8 KB
    __shared__ float2 Bs[8 * 32];    // [n][c]   2 KB
    int blk = blockIdx.x;
    int bm = blk >> 3, p = blk & 7;
    if (t < 64) {
        float s, c;
        sincospif(-(float)t / 32.0f, &s, &c);
        tw[t] = make_float2(c, s);
    }
    {   // stage M_p
        const float4* msrc = (const float4*)(g_M + p * 1024);
        float4* mdst = (float4*)Ms;
        mdst[t]       = msrc[t];
        mdst[t + 256] = msrc[t + 256];
    }
    {   // stage A slice: g_A[bm][d2][p][c] -> As[d2][c]
        const float4* asrc = (const float4*)(g_A + (size_t)bm * 16384 + p * 32);
        float4* adst = (float4*)As;
        #pragma unroll
        for (int i = 0; i < 4; i++) {
            int idx = i * 256 + t;
            int d2 = idx >> 4, j = idx & 15;
            adst[idx] = asrc[(size_t)d2 * 128 + j];
        }
    }
    __syncthreads();
    int n = t >> 5, c = t & 31;
    float2 acc = make_float2(0.f, 0.f);
    #pragma unroll 8
    for (int d2 = 0; d2 < 64; d2++) {
        float2 a = As[d2 * 32 + c];
        float2 e = tw[(n * d2) & 63];
        acc.x += a.x * e.x - a.y * e.y;
        acc.y += a.x * e.y + a.y * e.x;
    }
    Bs[n * 32 + c] = acc;
    __syncthreads();
    int co = c;
    float2 u = make_float2(0.f, 0.f);
    #pragma unroll 8
    for (int cc = 0; cc < 32; cc++) {
        float2 bv = Bs[n * 32 + cc];                  // warp broadcast
        float2 mv = Ms[cc * 32 + co];
        u.x += bv.x * mv.x - bv.y * mv.y;
        u.y += bv.x * mv.y + bv.y * mv.x;
    }
    g_U1[(size_t)bm * 2048 + (n * 8 + p) * 32 + co] = u;
}

// ---------------------------------------------------------------------------
// K4: blocks [0,2048): one per (bm, d2). Contract n first into C[p][co],
//     then p-DFT to 64 d3 with float4 stores. blocks [2048,2304): zeros.
// ---------------------------------------------------------------------------
__global__ void inv_kernel(float* __restrict__ out) {
    int t = threadIdx.x;                              // 256
    if (blockIdx.x >= 2048) {
        zero_range((float4*)out, Z3, Z4, blockIdx.x - 2048, 256, 256, t);
        return;
    }
    __shared__ float2 tw[64];
    __shared__ float2 C[8 * 32];     // [p][co] 2 KB
    int blk = blockIdx.x;
    int bm = blk >> 6, d2 = blk & 63;
    if (t < 64) {
        float s, c;
        sincospif(-(float)t / 32.0f, &s, &c);         // e^{-2pi i t/64}
        tw[t] = make_float2(c, s);
    }
    __syncthreads();
    // phase A: C[p][co] = sum_n U1[bm][n][p][co] * e^{+2pi i n d2/64}
    {
        int p = t >> 5, co = t & 31;
        const float2* U = g_U1 + (size_t)bm * 2048 + p * 32 + co;
        float2 acc = make_float2(0.f, 0.f);
        #pragma unroll
        for (int n = 0; n < 8; n++) {
            float2 u = __ldg(U + n * 256);
            float2 e = tw[(n * d2) & 63];             // conj => e^{+i}
            acc.x += u.x * e.x + u.y * e.y;
            acc.y += u.y * e.x - u.x * e.y;
        }
        C[p * 32 + co] = acc;
    }
    __syncthreads();
    // phase B: out[d3][co] = Re sum_p C[p][co] * e^{+2pi i p d3/64}
    int co4 = (t & 7) * 4;
    int r = t >> 3;                                   // 0..31
    int b = bm >> 3, m = bm & 7;
    float* ob = out + (((size_t)(b * 64 + m) * 64 + d2) * 2048);
    #pragma unroll
    for (int h = 0; h < 2; h++) {
        int d3 = r + h * 32;
        float o0 = 0.f, o1 = 0.f, o2 = 0.f, o3 = 0.f;
        #pragma unroll
        for (int p = 0; p < 8; p++) {
            float2 e = tw[(p * d3) & 63];
            float2 c0 = C[p * 32 + co4 + 0];
            float2 c1 = C[p * 32 + co4 + 1];
            float2 c2 = C[p * 32 + co4 + 2];
            float2 c3 = C[p * 32 + co4 + 3];
            o0 += c0.x * e.x + c0.y * e.y;            // Re(c * e^{+i})
            o1 += c1.x * e.x + c1.y * e.y;
            o2 += c2.x * e.x + c2.y * e.y;
            o3 += c3.x * e.x + c3.y * e.y;
        }
        __stcs((float4*)(ob + (size_t)d3 * 32 + co4), make_float4(o0, o1, o2, o3));
    }
}

// ---------------------------------------------------------------------------
extern "C" void kernel_launch(void* const* d_in, const int* in_sizes, int n_in,
                              void* d_out, int out_size) {
    const float* x  = (const float*)d_in[0];
    const float* wr = (const float*)d_in[1];
    const float* wi = (const float*)d_in[2];
    float* out = (float*)d_out;

    fwd_d3<<<2336, 256>>>(x, wr, wi, out);   // DFT + wsum + zeros
    prep_M<<<136, 1024>>>(out);              // M build + zeros
    fwd_d2_mix<<<512, 256>>>(out);           // DFT+mix + zeros
    inv_kernel<<<2304, 256>>>(out);          // inverse + zeros
}

// round 5
// speedup vs baseline: 1.0818x; 1.0818x over previous
#include <cuda_runtime.h>
#include <math.h>

// B=4, D1=D2=D3=64, CIN=COUT=32, M1=M2=M3=8
// Exact linear-algebra pipeline (no full FFTs):
//   A[bm,d2,p,c]  = sum_d3 x[bm,d2,d3,c] e^{-2pi i p d3/64}   (m<8,p<8)
//   Bs[bm,n,p,c]  = sum_d2 A e^{-2pi i n d2/64}               (n<8)
//   U1[bm,n,p,co] = sum_c Bs * M_p[c,co]
//   out[bm,d2,d3,co] = Re sum_{n,p} U1 e^{+2pi i (n d2 + p d3)/64}; y[:,8:]=0.
// The 117MB zero region is written by extra blocks spread across all kernels.

#define NB 4
#define NC 32
#define NM 8

#define ZREG 1835008ull           // float4 per zero region (one per b)
#define Z1 2202112ull             // K1 share end (30%)
#define Z2 3302912ull             // K2 share end (+15%)
#define Z3 5137920ull             // K3 share end (+25%)
#define Z4 7340032ull             // total (+30%)

__device__ float2 g_A  [NB*NM*64*NM*NC];   // [bm][d2][p][c]  4 MB
__device__ float2 g_U1 [NB*NM*NM*NM*NC];   // [bm][n][p][co]  512 KB
__device__ float2 g_Ws [NM*NC*NC];         // [p][k][o]
__device__ float2 g_M  [NM*NC*NC];         // [p][c][co]

__device__ __forceinline__ void zero_range(float4* o4, size_t lo, size_t hi,
                                           int zb, int nzb, int nthreads, int t) {
    const float4 z = make_float4(0.f, 0.f, 0.f, 0.f);
    size_t step = (size_t)nzb * nthreads;
    #pragma unroll
    for (int b = 0; b < 4; b++) {
        size_t rlo = (size_t)b * ZREG;
        size_t rhi = rlo + ZREG;
        size_t s = lo > rlo ? lo : rlo;
        size_t e = hi < rhi ? hi : rhi;
        float4* base = o4 + (size_t)(b * 64 + 8) * 32768 - rlo;
        for (size_t i = s + (size_t)zb * nthreads + t; i < e; i += step)
            __stcs(base + i, z);
    }
}

// ---------------------------------------------------------------------------
// K1: blocks [0,2048): d3 forward DFT (64 -> 8 modes), one per (bm,d2).
//     Split-K: thread (half,p2,c) does modes p2 & p2+4 over 32 d3, then reduce.
//     blocks [2048,2080): Wsum.  blocks [2080,2336): zero share [0,Z1).
// ---------------------------------------------------------------------------
__global__ void fwd_d3(const float* __restrict__ x,
                       const float* __restrict__ wr, const float* __restrict__ wi,
                       float* __restrict__ out) {
    int t = threadIdx.x;                              // 256
    if (blockIdx.x >= 2080) {
        zero_range((float4*)out, 0, Z1, blockIdx.x - 2080, 256, 256, t);
        return;
    }
    if (blockIdx.x >= 2048) {
        int g = (blockIdx.x - 2048) * 256 + t;        // 0..8191
        int p = g & 7;
        int o = (g >> 3) & 31;
        int k = g >> 8;
        float sr = 0.f, si = 0.f;
        int base = (k * 32 + o) * 512 + p;
        #pragma unroll 8
        for (int ij = 0; ij < 64; ij++) {
            sr += wr[base + ij * 8];
            si += wi[base + ij * 8];
        }
        g_Ws[(p * 32 + k) * 32 + o] = make_float2(sr, si);
        return;
    }
    __shared__ float  xs[2048];
    __shared__ float2 tw[64];
    __shared__ float2 Ap[2 * 8 * 32];                 // partial [half][p][c]
    if (t < 64) {
        float s, c;
        sincospif(-(float)t / 32.0f, &s, &c);         // e^{-2pi i t/64}
        tw[t] = make_float2(c, s);
    }
    int blk = blockIdx.x;                             // (b*8+m)*64 + d2
    int bm = blk >> 6;
    int d2 = blk & 63;
    int b = bm >> 3, m = bm & 7;
    const float4* xin = (const float4*)(x + ((size_t)(b * 64 + m) * 64 + d2) * 2048);
    float4* xs4 = (float4*)xs;
    xs4[t]       = __ldcs(xin + t);
    xs4[t + 256] = __ldcs(xin + t + 256);
    __syncthreads();
    int c = t & 31, p2 = (t >> 5) & 3, half = t >> 7;
    float a0r = 0.f, a0i = 0.f, a1r = 0.f, a1i = 0.f;
    int d3lo = half * 32;
    #pragma unroll 8
    for (int dd = 0; dd < 32; dd++) {
        int d3 = d3lo + dd;
        float v = xs[d3 * 32 + c];
        float2 e0 = tw[(p2 * d3) & 63];
        float2 e1 = tw[((p2 + 4) * d3) & 63];
        a0r += v * e0.x; a0i += v * e0.y;
        a1r += v * e1.x; a1i += v * e1.y;
    }
    Ap[(half * 8 + p2) * 32 + c]     = make_float2(a0r, a0i);
    Ap[(half * 8 + p2 + 4) * 32 + c] = make_float2(a1r, a1i);
    __syncthreads();
    {   // combine halves, write g_A[blk][p][c]
        float2 u = Ap[t];                             // [0][p][c], t = p*32+c
        float2 v = Ap[256 + t];
        g_A[(size_t)blk * 256 + t] = make_float2(u.x + v.x, u.y + v.y);
    }
}

// ---------------------------------------------------------------------------
// K2: blocks [0,8): M_p = (1/131072) IDFT32 o Wsum_p o DFT32.
//     blocks [8,136): zero-fill share [Z1, Z2).   blockDim = 1024
// ---------------------------------------------------------------------------
__global__ void prep_M(float* __restrict__ out) {
    int t = threadIdx.x;                              // 1024
    if (blockIdx.x >= 8) {
        zero_range((float4*)out, Z1, Z2, blockIdx.x - 8, 128, 1024, t);
        return;
    }
    __shared__ float2 tw32[32];
    __shared__ float2 Ws[1024];
    __shared__ float2 P[1024];
    int p = blockIdx.x;
    if (t < 32) {
        float s, c;
        sincospif(-(float)t / 16.0f, &s, &c);
        tw32[t] = make_float2(c, s);
    }
    Ws[t] = g_Ws[p * 1024 + t];
    __syncthreads();
    {
        int o = t & 31, c = t >> 5;
        float2 acc = make_float2(0.f, 0.f);
        #pragma unroll 8
        for (int k = 0; k < 32; k++) {
            float2 e = tw32[(k * c) & 31];
            float2 w = Ws[k * 32 + o];
            acc.x += e.x * w.x - e.y * w.y;
            acc.y += e.x * w.y + e.y * w.x;
        }
        P[c * 32 + o] = acc;
    }
    __syncthreads();
    {
        int co = t & 31, c = t >> 5;
        float2 acc = make_float2(0.f, 0.f);
        #pragma unroll 8
        for (int o = 0; o < 32; o++) {
            float2 e = tw32[(o * co) & 31];
            float2 v = P[c * 32 + o];
            acc.x += v.x * e.x + v.y * e.y;   // v * conj(e)
            acc.y += v.y * e.x - v.x * e.y;
        }
        const float scale = 1.0f / 131072.0f;
        g_M[(p * 32 + c) * 32 + co] = make_float2(acc.x * scale, acc.y * scale);
    }
}

// ---------------------------------------------------------------------------
// K3: blocks [0,256): d2 forward DFT + channel mix, one per (bm,p).
//     Split-K phase 1: thread (half,n2,c) does modes n2 & n2+4 over 32 d2.
//     blocks [256,512): zero-fill share [Z2, Z3).
// ---------------------------------------------------------------------------
__global__ void fwd_d2_mix(float* __restrict__ out) {
    int t = threadIdx.x;
    if (blockIdx.x >= 256) {
        zero_range((float4*)out, Z2, Z3, blockIdx.x - 256, 256, 256, t);
        return;
    }
    __shared__ float2 tw[64];
    __shared__ float2 As[64 * 32];   // [d2][c] 16 KB
    __shared__ float2 Ms[32 * 32];   // [c][co]  8 KB
    __shared__ float2 Bp[2 * 8 * 32];// partial [half][n][c] 4 KB
    __shared__ float2 Bs[8 * 32];    // [n][c]   2 KB
    int blk = blockIdx.x;
    int bm = blk >> 3, p = blk & 7;
    if (t < 64) {
        float s, c;
        sincospif(-(float)t / 32.0f, &s, &c);
        tw[t] = make_float2(c, s);
    }
    {   // stage M_p
        const float4* msrc = (const float4*)(g_M + p * 1024);
        float4* mdst = (float4*)Ms;
        mdst[t]       = msrc[t];
        mdst[t + 256] = msrc[t + 256];
    }
    {   // stage A slice: g_A[bm][d2][p][c] -> As[d2][c]
        const float4* asrc = (const float4*)(g_A + (size_t)bm * 16384 + p * 32);
        float4* adst = (float4*)As;
        #pragma unroll
        for (int i = 0; i < 4; i++) {
            int idx = i * 256 + t;
            int d2 = idx >> 4, j = idx & 15;
            adst[idx] = asrc[(size_t)d2 * 128 + j];
        }
    }
    __syncthreads();
    {   // phase 1 split-K
        int c = t & 31, n2 = (t >> 5) & 3, half = t >> 7;
        float2 a0 = make_float2(0.f, 0.f), a1 = make_float2(0.f, 0.f);
        int d2lo = half * 32;
        #pragma unroll 8
        for (int dd = 0; dd < 32; dd++) {
            int d2 = d2lo + dd;
            float2 a = As[d2 * 32 + c];
            float2 e0 = tw[(n2 * d2) & 63];
            float2 e1 = tw[((n2 + 4) * d2) & 63];
            a0.x += a.x * e0.x - a.y * e0.y;
            a0.y += a.x * e0.y + a.y * e0.x;
            a1.x += a.x * e1.x - a.y * e1.y;
            a1.y += a.x * e1.y + a.y * e1.x;
        }
        Bp[(half * 8 + n2) * 32 + c]     = a0;
        Bp[(half * 8 + n2 + 4) * 32 + c] = a1;
    }
    __syncthreads();
    {   // reduce halves
        float2 u = Bp[t], v = Bp[256 + t];
        Bs[t] = make_float2(u.x + v.x, u.y + v.y);    // t = n*32+c
    }
    __syncthreads();
    {   // mix: U1[bm][n][p][co] = sum_c Bs[n][c] * Ms[c][co]
        int n = t >> 5, co = t & 31;
        float2 u = make_float2(0.f, 0.f);
        #pragma unroll 8
        for (int cc = 0; cc < 32; cc++) {
            float2 bv = Bs[n * 32 + cc];              // warp broadcast
            float2 mv = Ms[cc * 32 + co];
            u.x += bv.x * mv.x - bv.y * mv.y;
            u.y += bv.x * mv.y + bv.y * mv.x;
        }
        g_U1[(size_t)bm * 2048 + (n * 8 + p) * 32 + co] = u;
    }
}

// ---------------------------------------------------------------------------
// K4: blocks [0,2048): one per (bm, d2). Contract n into C[p][co], then the
//     p-DFT with warp-uniform d3 (tw broadcasts) and register-cached C.
//     blocks [2048,2304): zero share [Z3, Z4).
// ---------------------------------------------------------------------------
__global__ void inv_kernel(float* __restrict__ out) {
    int t = threadIdx.x;                              // 256
    if (blockIdx.x >= 2048) {
        zero_range((float4*)out, Z3, Z4, blockIdx.x - 2048, 256, 256, t);
        return;
    }
    __shared__ float2 tw[64];
    __shared__ float2 C[8 * 32];     // [p][co] 2 KB
    int blk = blockIdx.x;
    int bm = blk >> 6, d2 = blk & 63;
    if (t < 64) {
        float s, c;
        sincospif(-(float)t / 32.0f, &s, &c);         // e^{-2pi i t/64}
        tw[t] = make_float2(c, s);
    }
    __syncthreads();
    // phase A: C[p][co] = sum_n U1[bm][n][p][co] * e^{+2pi i n d2/64}
    {
        int p = t >> 5, co = t & 31;
        const float2* U = g_U1 + (size_t)bm * 2048 + p * 32 + co;
        float2 acc = make_float2(0.f, 0.f);
        #pragma unroll
        for (int n = 0; n < 8; n++) {
            float2 u = __ldg(U + n * 256);
            float2 e = tw[(n * d2) & 63];             // conj => e^{+i}
            acc.x += u.x * e.x + u.y * e.y;
            acc.y += u.y * e.x - u.x * e.y;
        }
        C[p * 32 + co] = acc;
    }
    __syncthreads();
    // phase B: thread (q,co): 8 outputs at d3 = q*8+dd (d3 uniform per warp).
    int co = t & 31, q = t >> 5;
    float2 creg[8];
    #pragma unroll
    for (int p = 0; p < 8; p++) creg[p] = C[p * 32 + co];  // conflict-free
    int b = bm >> 3, m = bm & 7;
    float* ob = out + (((size_t)(b * 64 + m) * 64 + d2) * 2048) + co;
    #pragma unroll
    for (int dd = 0; dd < 8; dd++) {
        int d3 = q * 8 + dd;                          // warp-uniform
        float acc = 0.f;
        #pragma unroll
        for (int p = 0; p < 8; p++) {
            float2 e = tw[(p * d3) & 63];             // broadcast LDS
            acc += creg[p].x * e.x + creg[p].y * e.y; // Re(c * e^{+i})
        }
        __stcs(ob + (size_t)d3 * 32, acc);            // 128B/warp coalesced
    }
}

// ---------------------------------------------------------------------------
extern "C" void kernel_launch(void* const* d_in, const int* in_sizes, int n_in,
                              void* d_out, int out_size) {
    const float* x  = (const float*)d_in[0];
    const float* wr = (const float*)d_in[1];
    const float* wi = (const float*)d_in[2];
    float* out = (float*)d_out;

    fwd_d3<<<2336, 256>>>(x, wr, wi, out);   // DFT + wsum + zeros
    prep_M<<<136, 1024>>>(out);              // M build + zeros
    fwd_d2_mix<<<512, 256>>>(out);           // DFT+mix + zeros
    inv_kernel<<<2304, 256>>>(out);          // inverse + zeros
}

// round 6
// speedup vs baseline: 1.2081x; 1.1168x over previous
#include <cuda_runtime.h>
#include <math.h>

// B=4, D1=D2=D3=64, CIN=COUT=32, M1=M2=M3=8
// Exact linear-algebra pipeline (no full FFTs), radix-4 twiddle symmetry:
//   A[bm,d2,p,c]  = sum_d3 x e^{-2pi i p d3/64}   (m<8,p<8)
//   Bs[bm,n,p,c]  = sum_d2 A e^{-2pi i n d2/64}   (n<8)
//   U1[bm,n,p,co] = sum_c Bs * M_p[c,co]
//   out = Re sum_{n,p} U1 e^{+2pi i (n d2 + p d3)/64}; y[:,8:]=0.

#define NB 4
#define NC 32
#define NM 8

#define ZREG 1835008ull           // float4 per zero region (one per b)
#define Z1 2202112ull             // K1 share end (30%)
#define Z2 3302912ull             // K2 share end (+15%)
#define Z3 5137920ull             // K3 share end (+25%)
#define Z4 7340032ull             // total (+30%)

__device__ float2 g_A  [NB*NM*64*NM*NC];   // [bm][d2][p][c]  4 MB
__device__ float2 g_U1 [NB*NM*NM*NM*NC];   // [bm][n][p][co]  512 KB
__device__ float2 g_Ws [NM*NC*NC];         // [p][k][o]
__device__ float2 g_M  [NM*NC*NC];         // [p][c][co]

__device__ __forceinline__ void zero_range(float4* o4, size_t lo, size_t hi,
                                           int zb, int nzb, int nthreads, int t) {
    const float4 z = make_float4(0.f, 0.f, 0.f, 0.f);
    size_t step = (size_t)nzb * nthreads;
    #pragma unroll
    for (int b = 0; b < 4; b++) {
        size_t rlo = (size_t)b * ZREG;
        size_t rhi = rlo + ZREG;
        size_t s = lo > rlo ? lo : rlo;
        size_t e = hi < rhi ? hi : rhi;
        float4* base = o4 + (size_t)(b * 64 + 8) * 32768 - rlo;
        for (size_t i = s + (size_t)zb * nthreads + t; i < e; i += step)
            __stcs(base + i, z);
    }
}

// ---------------------------------------------------------------------------
// K1: blocks [0,2048): d3 forward DFT (64->8), radix-4: x[s+16k] combos.
//     blocks [2048,2080): Wsum.  blocks [2080,2336): zero share [0,Z1).
// ---------------------------------------------------------------------------
__global__ void fwd_d3(const float* __restrict__ x,
                       const float* __restrict__ wr, const float* __restrict__ wi,
                       float* __restrict__ out) {
    int t = threadIdx.x;                              // 256
    if (blockIdx.x >= 2080) {
        zero_range((float4*)out, 0, Z1, blockIdx.x - 2080, 256, 256, t);
        return;
    }
    if (blockIdx.x >= 2048) {
        int g = (blockIdx.x - 2048) * 256 + t;        // 0..8191
        int p = g & 7;
        int o = (g >> 3) & 31;
        int k = g >> 8;
        float sr = 0.f, si = 0.f;
        int base = (k * 32 + o) * 512 + p;
        #pragma unroll 8
        for (int ij = 0; ij < 64; ij++) {
            sr += wr[base + ij * 8];
            si += wi[base + ij * 8];
        }
        g_Ws[(p * 32 + k) * 32 + o] = make_float2(sr, si);
        return;
    }
    __shared__ float  xs[2048];
    __shared__ float2 tw[64];
    __shared__ float  Ye[2][16][32];                  // p mod4 = 0 / 2 inputs
    __shared__ float2 Yd[16][32];                     // (d0,d1) for odd p
    if (t < 64) {
        float s, c;
        sincospif(-(float)t / 32.0f, &s, &c);         // e^{-2pi i t/64}
        tw[t] = make_float2(c, s);
    }
    int blk = blockIdx.x;                             // bm*64 + d2
    int bm = blk >> 6;
    int d2 = blk & 63;
    int b = bm >> 3, m = bm & 7;
    const float4* xin = (const float4*)(x + ((size_t)(b * 64 + m) * 64 + d2) * 2048);
    float4* xs4 = (float4*)xs;
    xs4[t]       = __ldcs(xin + t);
    xs4[t + 256] = __ldcs(xin + t + 256);
    __syncthreads();
    // stage 1: radix-4 input combos, 2 (s,c) pairs per thread
    #pragma unroll
    for (int i = 0; i < 2; i++) {
        int idx = i * 256 + t;                        // 512 pairs
        int s = idx >> 5, c = idx & 31;
        float x0 = xs[s * 32 + c];
        float x1 = xs[(s + 16) * 32 + c];
        float x2 = xs[(s + 32) * 32 + c];
        float x3 = xs[(s + 48) * 32 + c];
        float s0 = x0 + x2, s1 = x1 + x3;
        float d0 = x0 - x2, d1 = x1 - x3;
        Ye[0][s][c] = s0 + s1;                        // p%4==0
        Ye[1][s][c] = s0 - s1;                        // p%4==2
        Yd[s][c] = make_float2(d0, d1);               // p odd
    }
    __syncthreads();
    // stage 2: A[p] = sum_s e^{-2pi i p s/64} * combo_p(s)
    int p = t >> 5, c = t & 31;
    float2 acc = make_float2(0.f, 0.f);
    int pm4 = p & 3;
    if (pm4 == 0 || pm4 == 2) {
        const float* Y = &Ye[pm4 >> 1][0][0];
        #pragma unroll
        for (int s = 0; s < 16; s++) {
            float v = Y[s * 32 + c];
            float2 e = tw[(p * s) & 63];
            acc.x += v * e.x;
            acc.y += v * e.y;
        }
    } else {
        float sg = (pm4 == 1) ? -1.f : 1.f;           // z = (d0, sg*d1)... p%4==1: d0 - i d1
        #pragma unroll
        for (int s = 0; s < 16; s++) {
            float2 d = Yd[s][c];
            float zx = d.x, zy = sg * d.y;
            float2 e = tw[(p * s) & 63];
            acc.x += zx * e.x - zy * e.y;
            acc.y += zx * e.y + zy * e.x;
        }
    }
    g_A[(size_t)blk * 256 + t] = acc;                 // t = p*32+c
}

// ---------------------------------------------------------------------------
// K2: blocks [0,8): M_p = (1/131072) IDFT32 o Wsum_p o DFT32.
//     blocks [8,136): zero-fill share [Z1, Z2).   blockDim = 1024
// ---------------------------------------------------------------------------
__global__ void prep_M(float* __restrict__ out) {
    int t = threadIdx.x;                              // 1024
    if (blockIdx.x >= 8) {
        zero_range((float4*)out, Z1, Z2, blockIdx.x - 8, 128, 1024, t);
        return;
    }
    __shared__ float2 tw32[32];
    __shared__ float2 Ws[1024];
    __shared__ float2 P[1024];
    int p = blockIdx.x;
    if (t < 32) {
        float s, c;
        sincospif(-(float)t / 16.0f, &s, &c);
        tw32[t] = make_float2(c, s);
    }
    Ws[t] = g_Ws[p * 1024 + t];
    __syncthreads();
    {
        int o = t & 31, c = t >> 5;
        float2 acc = make_float2(0.f, 0.f);
        #pragma unroll 8
        for (int k = 0; k < 32; k++) {
            float2 e = tw32[(k * c) & 31];
            float2 w = Ws[k * 32 + o];
            acc.x += e.x * w.x - e.y * w.y;
            acc.y += e.x * w.y + e.y * w.x;
        }
        P[c * 32 + o] = acc;
    }
    __syncthreads();
    {
        int co = t & 31, c = t >> 5;
        float2 acc = make_float2(0.f, 0.f);
        #pragma unroll 8
        for (int o = 0; o < 32; o++) {
            float2 e = tw32[(o * co) & 31];
            float2 v = P[c * 32 + o];
            acc.x += v.x * e.x + v.y * e.y;   // v * conj(e)
            acc.y += v.y * e.x - v.x * e.y;
        }
        const float scale = 1.0f / 131072.0f;
        g_M[(p * 32 + c) * 32 + co] = make_float2(acc.x * scale, acc.y * scale);
    }
}

// ---------------------------------------------------------------------------
// K3: blocks [0,256): d2 forward DFT (radix-4) + channel mix, one per (bm,p).
//     blocks [256,512): zero-fill share [Z2, Z3).
// ---------------------------------------------------------------------------
__global__ void fwd_d2_mix(float* __restrict__ out) {
    int t = threadIdx.x;
    if (blockIdx.x >= 256) {
        zero_range((float4*)out, Z2, Z3, blockIdx.x - 256, 256, 256, t);
        return;
    }
    __shared__ float2 tw[64];
    __shared__ float2 As[64 * 32];   // [d2][c] 16 KB
    __shared__ float2 Ms[32 * 32];   // [c][co]  8 KB
    __shared__ float2 Ze[2][16][32]; // even-n combos 8 KB
    __shared__ float2 Zd0[16][32];   // d0 (complex) 4 KB
    __shared__ float2 Zd1[16][32];   // d1 (complex) 4 KB
    __shared__ float2 Bs[8 * 32];    // [n][c] 2 KB
    int blk = blockIdx.x;
    int bm = blk >> 3, p = blk & 7;
    if (t < 64) {
        float s, c;
        sincospif(-(float)t / 32.0f, &s, &c);
        tw[t] = make_float2(c, s);
    }
    {   // stage M_p
        const float4* msrc = (const float4*)(g_M + p * 1024);
        float4* mdst = (float4*)Ms;
        mdst[t]       = msrc[t];
        mdst[t + 256] = msrc[t + 256];
    }
    {   // stage A slice: g_A[bm][d2][p][c] -> As[d2][c]
        const float4* asrc = (const float4*)(g_A + (size_t)bm * 16384 + p * 32);
        float4* adst = (float4*)As;
        #pragma unroll
        for (int i = 0; i < 4; i++) {
            int idx = i * 256 + t;
            int d2 = idx >> 4, j = idx & 15;
            adst[idx] = asrc[(size_t)d2 * 128 + j];
        }
    }
    __syncthreads();
    // stage 1: radix-4 combos over d2 = s + 16k (complex)
    #pragma unroll
    for (int i = 0; i < 2; i++) {
        int idx = i * 256 + t;
        int s = idx >> 5, c = idx & 31;
        float2 a0 = As[s * 32 + c];
        float2 a1 = As[(s + 16) * 32 + c];
        float2 a2 = As[(s + 32) * 32 + c];
        float2 a3 = As[(s + 48) * 32 + c];
        float2 s0 = make_float2(a0.x + a2.x, a0.y + a2.y);
        float2 s1 = make_float2(a1.x + a3.x, a1.y + a3.y);
        float2 d0 = make_float2(a0.x - a2.x, a0.y - a2.y);
        float2 d1 = make_float2(a1.x - a3.x, a1.y - a3.y);
        Ze[0][s][c] = make_float2(s0.x + s1.x, s0.y + s1.y);  // n%4==0
        Ze[1][s][c] = make_float2(s0.x - s1.x, s0.y - s1.y);  // n%4==2
        Zd0[s][c] = d0;
        Zd1[s][c] = d1;
    }
    __syncthreads();
    {   // stage 2: Bs[n][c] = sum_s e^{-2pi i n s/64} * combo_n(s)
        int n = t >> 5, c = t & 31;
        float2 acc = make_float2(0.f, 0.f);
        int nm4 = n & 3;
        if (nm4 == 0 || nm4 == 2) {
            const float2* Z = &Ze[nm4 >> 1][0][0];
            #pragma unroll
            for (int s = 0; s < 16; s++) {
                float2 z = Z[s * 32 + c];
                float2 e = tw[(n * s) & 63];
                acc.x += z.x * e.x - z.y * e.y;
                acc.y += z.x * e.y + z.y * e.x;
            }
        } else {
            float sg = (nm4 == 1) ? -1.f : 1.f;       // n%4==1: d0 - i d1; ==3: d0 + i d1
            #pragma unroll
            for (int s = 0; s < 16; s++) {
                float2 d0 = Zd0[s][c];
                float2 d1 = Zd1[s][c];
                float zx = d0.x - sg * d1.y;          // d0 + sg*i*d1
                float zy = d0.y + sg * d1.x;
                float2 e = tw[(n * s) & 63];
                acc.x += zx * e.x - zy * e.y;
                acc.y += zx * e.y + zy * e.x;
            }
        }
        Bs[n * 32 + c] = acc;
    }
    __syncthreads();
    {   // mix: U1[bm][n][p][co] = sum_c Bs[n][c] * Ms[c][co]
        int n = t >> 5, co = t & 31;
        float2 u = make_float2(0.f, 0.f);
        #pragma unroll 8
        for (int cc = 0; cc < 32; cc++) {
            float2 bv = Bs[n * 32 + cc];              // warp broadcast
            float2 mv = Ms[cc * 32 + co];
            u.x += bv.x * mv.x - bv.y * mv.y;
            u.y += bv.x * mv.y + bv.y * mv.x;
        }
        g_U1[(size_t)bm * 2048 + (n * 8 + p) * 32 + co] = u;
    }
}

// ---------------------------------------------------------------------------
// K4: blocks [0,2048): one per (bm, d2). Phase A: contract n into C[p][co].
//     Phase B: radix-4 output DFT — one (R,I) set per base s gives 4 d3.
//     blocks [2048,2304): zero share [Z3, Z4).
// ---------------------------------------------------------------------------
__global__ void inv_kernel(float* __restrict__ out) {
    int t = threadIdx.x;                              // 256
    if (blockIdx.x >= 2048) {
        zero_range((float4*)out, Z3, Z4, blockIdx.x - 2048, 256, 256, t);
        return;
    }
    __shared__ float2 tw[64];
    __shared__ float2 C[8 * 32];     // [p][co] 2 KB
    int blk = blockIdx.x;
    int bm = blk >> 6, d2 = blk & 63;
    if (t < 64) {
        float s, c;
        sincospif(-(float)t / 32.0f, &s, &c);         // e^{-2pi i t/64}
        tw[t] = make_float2(c, s);
    }
    __syncthreads();
    // phase A: C[p][co] = sum_n U1[bm][n][p][co] * e^{+2pi i n d2/64}
    {
        int p = t >> 5, co = t & 31;
        const float2* U = g_U1 + (size_t)bm * 2048 + p * 32 + co;
        float2 acc = make_float2(0.f, 0.f);
        #pragma unroll
        for (int n = 0; n < 8; n++) {
            float2 u = __ldg(U + n * 256);
            float2 e = tw[(n * d2) & 63];             // conj => e^{+i}
            acc.x += u.x * e.x + u.y * e.y;
            acc.y += u.y * e.x - u.x * e.y;
        }
        C[p * 32 + co] = acc;
    }
    __syncthreads();
    // phase B: thread (r,co), bases s = r, r+8; each base yields 4 d3 outputs.
    int co = t & 31, r = t >> 5;
    float2 cr[8];
    #pragma unroll
    for (int p = 0; p < 8; p++) cr[p] = C[p * 32 + co];   // conflict-free
    int b = bm >> 3, m = bm & 7;
    float* ob = out + (((size_t)(b * 64 + m) * 64 + d2) * 2048) + co;
    #pragma unroll
    for (int h = 0; h < 2; h++) {
        int s = r + h * 8;                            // warp-uniform base
        float R[8], I1, I3, I5, I7;
        #pragma unroll
        for (int p = 0; p < 8; p++) {
            float2 e = tw[(p * s) & 63];              // broadcast LDS
            R[p] = cr[p].x * e.x + cr[p].y * e.y;     // Re(C e^{+i})
            if (p == 1) I1 = cr[1].y * e.x - cr[1].x * e.y;
            if (p == 3) I3 = cr[3].y * e.x - cr[3].x * e.y;
            if (p == 5) I5 = cr[5].y * e.x - cr[5].x * e.y;
            if (p == 7) I7 = cr[7].y * e.x - cr[7].x * e.y;
        }
        float RA = R[0] + R[4], RB = R[2] + R[6];
        float RC = R[1] + R[5], RD = R[3] + R[7];
        float REm = RA - RB;
        float IA = (I3 + I7) - (I1 + I5);
        __stcs(ob + (size_t)(s      ) * 32, RA + RB + RC + RD);
        __stcs(ob + (size_t)(s + 16) * 32, REm + IA);
        __stcs(ob + (size_t)(s + 32) * 32, RA + RB - RC - RD);
        __stcs(ob + (size_t)(s + 48) * 32, REm - IA);
    }
}

// ---------------------------------------------------------------------------
extern "C" void kernel_launch(void* const* d_in, const int* in_sizes, int n_in,
                              void* d_out, int out_size) {
    const float* x  = (const float*)d_in[0];
    const float* wr = (const float*)d_in[1];
    const float* wi = (const float*)d_in[2];
    float* out = (float*)d_out;

    fwd_d3<<<2336, 256>>>(x, wr, wi, out);   // DFT + wsum + zeros
    prep_M<<<136, 1024>>>(out);              // M build + zeros
    fwd_d2_mix<<<512, 256>>>(out);           // DFT+mix + zeros
    inv_kernel<<<2304, 256>>>(out);          // inverse + zeros
}

// round 7
// speedup vs baseline: 1.3101x; 1.0844x over previous
#include <cuda_runtime.h>
#include <math.h>

// B=4, D1=D2=D3=64, CIN=COUT=32, M1=M2=M3=8
// Exact linear-algebra pipeline (no full FFTs), radix-4 twiddle symmetry:
//   A[bm,d2,p,c]  = sum_d3 x e^{-2pi i p d3/64}   (m<8,p<8)
//   Bs[bm,n,p,c]  = sum_d2 A e^{-2pi i n d2/64}   (n<8)
//   U1[bm,n,p,co] = sum_c Bs * M_p[c,co]
//   out = Re sum_{n,p} U1 e^{+2pi i (n d2 + p d3)/64}; y[:,8:]=0.

#define NB 4
#define NC 32
#define NM 8

#define ZREG 1835008ull           // float4 per zero region (one per b)
#define Z1 2202112ull             // K1 share end (30%)
#define Z2 3302912ull             // K2 share end (+15%)
#define Z3 5137920ull             // K3 share end (+25%)
#define Z4 7340032ull             // total (+30%)

__device__ float2 g_A  [NB*NM*64*NM*NC];   // [bm][d2][p][c]  4 MB
__device__ float2 g_U1 [NB*NM*NM*NM*NC];   // [bm][n][p][co]  512 KB
__device__ float2 g_Ws [NM*NC*NC];         // [p][k][o]
__device__ float2 g_M  [NM*NC*NC];         // [p][c][co]

__device__ __forceinline__ void zero_range(float4* o4, size_t lo, size_t hi,
                                           int zb, int nzb, int nthreads, int t) {
    const float4 z = make_float4(0.f, 0.f, 0.f, 0.f);
    size_t step = (size_t)nzb * nthreads;
    #pragma unroll
    for (int b = 0; b < 4; b++) {
        size_t rlo = (size_t)b * ZREG;
        size_t rhi = rlo + ZREG;
        size_t s = lo > rlo ? lo : rlo;
        size_t e = hi < rhi ? hi : rhi;
        float4* base = o4 + (size_t)(b * 64 + 8) * 32768 - rlo;
        for (size_t i = s + (size_t)zb * nthreads + t; i < e; i += step)
            __stcs(base + i, z);
    }
}

// ---------------------------------------------------------------------------
// K1: blocks [0,2048): d3 forward DFT (64->8), radix-4: x[s+16k] combos.
//     blocks [2048,2080): Wsum.  blocks [2080,2336): zero share [0,Z1).
// ---------------------------------------------------------------------------
__global__ void fwd_d3(const float* __restrict__ x,
                       const float* __restrict__ wr, const float* __restrict__ wi,
                       float* __restrict__ out) {
    int t = threadIdx.x;                              // 256
    if (blockIdx.x >= 2080) {
        zero_range((float4*)out, 0, Z1, blockIdx.x - 2080, 256, 256, t);
        return;
    }
    if (blockIdx.x >= 2048) {
        int g = (blockIdx.x - 2048) * 256 + t;        // 0..8191
        int p = g & 7;
        int o = (g >> 3) & 31;
        int k = g >> 8;
        float sr = 0.f, si = 0.f;
        int base = (k * 32 + o) * 512 + p;
        #pragma unroll 8
        for (int ij = 0; ij < 64; ij++) {
            sr += wr[base + ij * 8];
            si += wi[base + ij * 8];
        }
        g_Ws[(p * 32 + k) * 32 + o] = make_float2(sr, si);
        return;
    }
    __shared__ float  xs[2048];
    __shared__ float2 tw[64];
    __shared__ float  Ye[2][16][32];                  // p mod4 = 0 / 2 inputs
    __shared__ float2 Yd[16][32];                     // (d0,d1) for odd p
    if (t < 64) {
        float s, c;
        sincospif(-(float)t / 32.0f, &s, &c);         // e^{-2pi i t/64}
        tw[t] = make_float2(c, s);
    }
    int blk = blockIdx.x;                             // bm*64 + d2
    int bm = blk >> 6;
    int d2 = blk & 63;
    int b = bm >> 3, m = bm & 7;
    const float4* xin = (const float4*)(x + ((size_t)(b * 64 + m) * 64 + d2) * 2048);
    float4* xs4 = (float4*)xs;
    xs4[t]       = __ldcs(xin + t);
    xs4[t + 256] = __ldcs(xin + t + 256);
    __syncthreads();
    // stage 1: radix-4 input combos, 2 (s,c) pairs per thread
    #pragma unroll
    for (int i = 0; i < 2; i++) {
        int idx = i * 256 + t;                        // 512 pairs
        int s = idx >> 5, c = idx & 31;
        float x0 = xs[s * 32 + c];
        float x1 = xs[(s + 16) * 32 + c];
        float x2 = xs[(s + 32) * 32 + c];
        float x3 = xs[(s + 48) * 32 + c];
        float s0 = x0 + x2, s1 = x1 + x3;
        float d0 = x0 - x2, d1 = x1 - x3;
        Ye[0][s][c] = s0 + s1;                        // p%4==0
        Ye[1][s][c] = s0 - s1;                        // p%4==2
        Yd[s][c] = make_float2(d0, d1);               // p odd
    }
    __syncthreads();
    // stage 2: A[p] = sum_s e^{-2pi i p s/64} * combo_p(s)
    int p = t >> 5, c = t & 31;
    float2 acc = make_float2(0.f, 0.f);
    int pm4 = p & 3;
    if (pm4 == 0 || pm4 == 2) {
        const float* Y = &Ye[pm4 >> 1][0][0];
        #pragma unroll
        for (int s = 0; s < 16; s++) {
            float v = Y[s * 32 + c];
            float2 e = tw[(p * s) & 63];
            acc.x += v * e.x;
            acc.y += v * e.y;
        }
    } else {
        float sg = (pm4 == 1) ? -1.f : 1.f;
        #pragma unroll
        for (int s = 0; s < 16; s++) {
            float2 d = Yd[s][c];
            float zx = d.x, zy = sg * d.y;
            float2 e = tw[(p * s) & 63];
            acc.x += zx * e.x - zy * e.y;
            acc.y += zx * e.y + zy * e.x;
        }
    }
    g_A[(size_t)blk * 256 + t] = acc;                 // t = p*32+c
}

// ---------------------------------------------------------------------------
// K2: blocks [0,8): M_p = (1/131072) IDFT32 o Wsum_p o DFT32.
//     blocks [8,136): zero-fill share [Z1, Z2).   blockDim = 1024
// ---------------------------------------------------------------------------
__global__ void prep_M(float* __restrict__ out) {
    int t = threadIdx.x;                              // 1024
    if (blockIdx.x >= 8) {
        zero_range((float4*)out, Z1, Z2, blockIdx.x - 8, 128, 1024, t);
        return;
    }
    __shared__ float2 tw32[32];
    __shared__ float2 Ws[1024];
    __shared__ float2 P[1024];
    int p = blockIdx.x;
    if (t < 32) {
        float s, c;
        sincospif(-(float)t / 16.0f, &s, &c);
        tw32[t] = make_float2(c, s);
    }
    Ws[t] = g_Ws[p * 1024 + t];
    __syncthreads();
    {
        int o = t & 31, c = t >> 5;
        float2 acc = make_float2(0.f, 0.f);
        #pragma unroll 8
        for (int k = 0; k < 32; k++) {
            float2 e = tw32[(k * c) & 31];
            float2 w = Ws[k * 32 + o];
            acc.x += e.x * w.x - e.y * w.y;
            acc.y += e.x * w.y + e.y * w.x;
        }
        P[c * 32 + o] = acc;
    }
    __syncthreads();
    {
        int co = t & 31, c = t >> 5;
        float2 acc = make_float2(0.f, 0.f);
        #pragma unroll 8
        for (int o = 0; o < 32; o++) {
            float2 e = tw32[(o * co) & 31];
            float2 v = P[c * 32 + o];
            acc.x += v.x * e.x + v.y * e.y;   // v * conj(e)
            acc.y += v.y * e.x - v.x * e.y;
        }
        const float scale = 1.0f / 131072.0f;
        g_M[(p * 32 + c) * 32 + co] = make_float2(acc.x * scale, acc.y * scale);
    }
}

// ---------------------------------------------------------------------------
// K3: blocks [0,256): d2 forward DFT (radix-4) + channel mix, one per (bm,p).
//     blocks [256,512): zero-fill share [Z2, Z3).
// ---------------------------------------------------------------------------
__global__ void fwd_d2_mix(float* __restrict__ out) {
    int t = threadIdx.x;
    if (blockIdx.x >= 256) {
        zero_range((float4*)out, Z2, Z3, blockIdx.x - 256, 256, 256, t);
        return;
    }
    __shared__ float2 tw[64];
    __shared__ float2 As[64 * 32];   // [d2][c] 16 KB
    __shared__ float2 Ms[32 * 32];   // [c][co]  8 KB
    __shared__ float2 Ze[2][16][32]; // even-n combos 8 KB
    __shared__ float2 Zd0[16][32];   // d0 (complex) 4 KB
    __shared__ float2 Zd1[16][32];   // d1 (complex) 4 KB
    __shared__ float2 Bs[8 * 32];    // [n][c] 2 KB
    int blk = blockIdx.x;
    int bm = blk >> 3, p = blk & 7;
    if (t < 64) {
        float s, c;
        sincospif(-(float)t / 32.0f, &s, &c);
        tw[t] = make_float2(c, s);
    }
    {   // stage M_p
        const float4* msrc = (const float4*)(g_M + p * 1024);
        float4* mdst = (float4*)Ms;
        mdst[t]       = msrc[t];
        mdst[t + 256] = msrc[t + 256];
    }
    {   // stage A slice: g_A[bm][d2][p][c] -> As[d2][c]
        const float4* asrc = (const float4*)(g_A + (size_t)bm * 16384 + p * 32);
        float4* adst = (float4*)As;
        #pragma unroll
        for (int i = 0; i < 4; i++) {
            int idx = i * 256 + t;
            int d2 = idx >> 4, j = idx & 15;
            adst[idx] = asrc[(size_t)d2 * 128 + j];
        }
    }
    __syncthreads();
    // stage 1: radix-4 combos over d2 = s + 16k (complex)
    #pragma unroll
    for (int i = 0; i < 2; i++) {
        int idx = i * 256 + t;
        int s = idx >> 5, c = idx & 31;
        float2 a0 = As[s * 32 + c];
        float2 a1 = As[(s + 16) * 32 + c];
        float2 a2 = As[(s + 32) * 32 + c];
        float2 a3 = As[(s + 48) * 32 + c];
        float2 s0 = make_float2(a0.x + a2.x, a0.y + a2.y);
        float2 s1 = make_float2(a1.x + a3.x, a1.y + a3.y);
        float2 d0 = make_float2(a0.x - a2.x, a0.y - a2.y);
        float2 d1 = make_float2(a1.x - a3.x, a1.y - a3.y);
        Ze[0][s][c] = make_float2(s0.x + s1.x, s0.y + s1.y);  // n%4==0
        Ze[1][s][c] = make_float2(s0.x - s1.x, s0.y - s1.y);  // n%4==2
        Zd0[s][c] = d0;
        Zd1[s][c] = d1;
    }
    __syncthreads();
    {   // stage 2: Bs[n][c] = sum_s e^{-2pi i n s/64} * combo_n(s)
        int n = t >> 5, c = t & 31;
        float2 acc = make_float2(0.f, 0.f);
        int nm4 = n & 3;
        if (nm4 == 0 || nm4 == 2) {
            const float2* Z = &Ze[nm4 >> 1][0][0];
            #pragma unroll
            for (int s = 0; s < 16; s++) {
                float2 z = Z[s * 32 + c];
                float2 e = tw[(n * s) & 63];
                acc.x += z.x * e.x - z.y * e.y;
                acc.y += z.x * e.y + z.y * e.x;
            }
        } else {
            float sg = (nm4 == 1) ? -1.f : 1.f;
            #pragma unroll
            for (int s = 0; s < 16; s++) {
                float2 d0 = Zd0[s][c];
                float2 d1 = Zd1[s][c];
                float zx = d0.x - sg * d1.y;          // d0 + sg*i*d1
                float zy = d0.y + sg * d1.x;
                float2 e = tw[(n * s) & 63];
                acc.x += zx * e.x - zy * e.y;
                acc.y += zx * e.y + zy * e.x;
            }
        }
        Bs[n * 32 + c] = acc;
    }
    __syncthreads();
    {   // mix: U1[bm][n][p][co] = sum_c Bs[n][c] * Ms[c][co]
        int n = t >> 5, co = t & 31;
        float2 u = make_float2(0.f, 0.f);
        #pragma unroll 8
        for (int cc = 0; cc < 32; cc++) {
            float2 bv = Bs[n * 32 + cc];              // warp broadcast
            float2 mv = Ms[cc * 32 + co];
            u.x += bv.x * mv.x - bv.y * mv.y;
            u.y += bv.x * mv.y + bv.y * mv.x;
        }
        g_U1[(size_t)bm * 2048 + (n * 8 + p) * 32 + co] = u;
    }
}

// ---------------------------------------------------------------------------
// K4: blocks [0,512): one per (bm, d2-group-of-4). Phase A preloads U into
//     registers once, contracts n for 4 d2 values. Phase B: radix-4 output
//     DFT per d2. blocks [512,768): zero share [Z3, Z4).
// ---------------------------------------------------------------------------
__global__ void inv_kernel(float* __restrict__ out) {
    int t = threadIdx.x;                              // 256
    if (blockIdx.x >= 512) {
        zero_range((float4*)out, Z3, Z4, blockIdx.x - 512, 256, 256, t);
        return;
    }
    __shared__ float2 tw[64];
    __shared__ float2 C[4][8 * 32];  // [dd][p][co] 8 KB
    int blk = blockIdx.x;
    int bm = blk >> 4, d2g = blk & 15;                // d2 = d2g*4 + dd
    if (t < 64) {
        float s, c;
        sincospif(-(float)t / 32.0f, &s, &c);         // e^{-2pi i t/64}
        tw[t] = make_float2(c, s);
    }
    // preload U1[bm][n][p][co] for this (p,co) — shared across all 4 d2
    int p = t >> 5, co = t & 31;
    float2 u[8];
    {
        const float2* U = g_U1 + (size_t)bm * 2048 + p * 32 + co;
        #pragma unroll
        for (int n = 0; n < 8; n++) u[n] = __ldg(U + n * 256);
    }
    __syncthreads();
    // phase A: C[dd][p][co] = sum_n u[n] * e^{+2pi i n d2/64}
    #pragma unroll
    for (int dd = 0; dd < 4; dd++) {
        int d2 = d2g * 4 + dd;
        float2 acc = make_float2(0.f, 0.f);
        #pragma unroll
        for (int n = 0; n < 8; n++) {
            float2 e = tw[(n * d2) & 63];             // conj => e^{+i}
            acc.x += u[n].x * e.x + u[n].y * e.y;
            acc.y += u[n].y * e.x - u[n].x * e.y;
        }
        C[dd][p * 32 + co] = acc;
    }
    __syncthreads();
    // phase B: per d2, thread (r,co): bases s = r, r+8; each gives 4 d3.
    int r = t >> 5;
    int b = bm >> 3, m = bm & 7;
    float* obase = out + ((size_t)(b * 64 + m) * 64 + d2g * 4) * 2048 + co;
    #pragma unroll
    for (int dd = 0; dd < 4; dd++) {
        float2 cr[8];
        #pragma unroll
        for (int pp = 0; pp < 8; pp++) cr[pp] = C[dd][pp * 32 + co];
        float* ob = obase + (size_t)dd * 2048;
        #pragma unroll
        for (int h = 0; h < 2; h++) {
            int s = r + h * 8;                        // warp-uniform base
            float R[8], I1, I3, I5, I7;
            #pragma unroll
            for (int pp = 0; pp < 8; pp++) {
                float2 e = tw[(pp * s) & 63];         // broadcast LDS
                R[pp] = cr[pp].x * e.x + cr[pp].y * e.y;
                if (pp == 1) I1 = cr[1].y * e.x - cr[1].x * e.y;
                if (pp == 3) I3 = cr[3].y * e.x - cr[3].x * e.y;
                if (pp == 5) I5 = cr[5].y * e.x - cr[5].x * e.y;
                if (pp == 7) I7 = cr[7].y * e.x - cr[7].x * e.y;
            }
            float RA = R[0] + R[4], RB = R[2] + R[6];
            float RC = R[1] + R[5], RD = R[3] + R[7];
            float REm = RA - RB;
            float IA = (I3 + I7) - (I1 + I5);
            __stcs(ob + (size_t)(s      ) * 32, RA + RB + RC + RD);
            __stcs(ob + (size_t)(s + 16) * 32, REm + IA);
            __stcs(ob + (size_t)(s + 32) * 32, RA + RB - RC - RD);
            __stcs(ob + (size_t)(s + 48) * 32, REm - IA);
        }
    }
}

// ---------------------------------------------------------------------------
extern "C" void kernel_launch(void* const* d_in, const int* in_sizes, int n_in,
                              void* d_out, int out_size) {
    const float* x  = (const float*)d_in[0];
    const float* wr = (const float*)d_in[1];
    const float* wi = (const float*)d_in[2];
    float* out = (float*)d_out;

    fwd_d3<<<2336, 256>>>(x, wr, wi, out);   // DFT + wsum + zeros
    prep_M<<<136, 1024>>>(out);              // M build + zeros
    fwd_d2_mix<<<512, 256>>>(out);           // DFT+mix + zeros
    inv_kernel<<<768, 256>>>(out);           // inverse + zeros
}